// round 9
// baseline (speedup 1.0000x reference)
#include <cuda_runtime.h>

// ---------------------------------------------------------------------------
// Problem shape (fixed by setup_inputs): [B=4, C=16, T=32, H=128, W=128] fp32
// out = (total, L_main, L_temp) as 3 fp32 scalars.
//
// Math: with e = x_star - x_tgt (linearity), e_low = D^T(De) where D = first
// K=4 orthonormal DCT-II rows. Temporal-diff energy = c^T (Q Q^T) c with
// c = De, Q[n,s] = D[n,s+1]-D[n,s]. DC row of D is constant -> Q row 0 == 0,
// so only c1..c3 are needed. Charbonnier ~ |e| (abs error <= eps = 1e-6).
//
// R9 structure: grid = 592 = 148 SMs x 4 CTAs exactly -> every SM holds the
// same number of CTAs (R8's grid=512 left 80 SMs with 3 CTAs while 68 had 4,
// capping utilization at 512/592). 262144 fiber columns over 151552 threads:
// blocks 0..431 process TWO columns per thread (4 independent load streams,
// high MLP), blocks 432..591 process ONE. The split is on an exact block
// boundary (110592 = 432*256) -> no intra-block divergence, and the 160
// light blocks spread ~1 per SM under the bid%148 placement, so per-SM
// critical path drops from 8 column-units to 7.
// ---------------------------------------------------------------------------
constexpr int T_DIM  = 32;
constexpr int HW     = 128 * 128;      // 16384
constexpr int HW4    = HW / 4;         // 4096 float4 per (b,c,t) plane
constexpr int BC     = 4 * 16;         // 64
constexpr int BLOCK  = 256;
constexpr int NITEM  = BC * HW4;       // 262144 fiber columns (float4 wide)
constexpr int NBLK   = 148 * 4;        // 592 blocks: exactly 4 CTAs per SM
constexpr int STRIDE = NBLK * BLOCK;   // 151552 threads
constexpr int LIM2   = NITEM - STRIDE; // 110592 = 432*BLOCK: two-column cutoff

constexpr double N_MAIN = 33554432.0;  // B*C*T*H*W
constexpr double N_TEMP = 32505856.0;  // B*C*(T-1)*H*W
constexpr double TAU    = 0.1;

// ---------------------------------------------------------------------------
// Compile-time DCT: D[n][t] = 0.25 * cos(pi*(2t+1)*n/64)   (sqrt(2/32)=0.25)
// ---------------------------------------------------------------------------
constexpr double PI_D = 3.141592653589793238462643383279502884;

__host__ __device__ constexpr double dcos(double x) {
    while (x >  PI_D) x -= 2.0 * PI_D;
    while (x < -PI_D) x += 2.0 * PI_D;
    double x2 = x * x;
    double term = 1.0, sum = 1.0;
    for (int k = 1; k <= 18; ++k) {
        term *= -x2 / ((2.0 * k - 1.0) * (2.0 * k));
        sum += term;
    }
    return sum;
}
__host__ __device__ constexpr double Dc(int n, int t) {
    return 0.25 * dcos(PI_D * (2.0 * t + 1.0) * (double)n / 64.0);
}
__host__ __device__ constexpr double Qc(int n, int s) { return Dc(n, s + 1) - Dc(n, s); }
__host__ __device__ constexpr double Mc(int n, int m) {
    double s = 0.0;
    for (int i = 0; i < T_DIM - 1; ++i) s += Qc(n, i) * Qc(m, i);
    return s;
}

// ---------------------------------------------------------------------------
// Scratch: per-block partials + self-resetting completion counter.
// atomicInc(&g_count, NBLK-1) wraps to 0 when the last block arrives, so the
// counter is 0 again at the start of every graph replay. No cleanup kernel.
// ---------------------------------------------------------------------------
__device__ double   g_part_main[NBLK];
__device__ double   g_part_temp[NBLK];
__device__ unsigned g_count = 0;

struct Acc {
    float4 c1, c2, c3;
    float  m0, m1;   // pairwise |e| accumulators
};

__device__ __forceinline__ void proc(const float4& a, const float4& b,
                                     float d1, float d2, float d3, Acc& s) {
    float e0 = a.x - b.x, e1 = a.y - b.y, e2 = a.z - b.z, e3 = a.w - b.w;
    s.m0 += fabsf(e0) + fabsf(e1);
    s.m1 += fabsf(e2) + fabsf(e3);
    s.c1.x = fmaf(d1, e0, s.c1.x); s.c1.y = fmaf(d1, e1, s.c1.y);
    s.c1.z = fmaf(d1, e2, s.c1.z); s.c1.w = fmaf(d1, e3, s.c1.w);
    s.c2.x = fmaf(d2, e0, s.c2.x); s.c2.y = fmaf(d2, e1, s.c2.y);
    s.c2.z = fmaf(d2, e2, s.c2.z); s.c2.w = fmaf(d2, e3, s.c2.w);
    s.c3.x = fmaf(d3, e0, s.c3.x); s.c3.y = fmaf(d3, e1, s.c3.y);
    s.c3.z = fmaf(d3, e2, s.c3.z); s.c3.w = fmaf(d3, e3, s.c3.w);
}

// Template-unrolled T loop: coefficients are constexpr locals per step ->
// FFMA immediates in SASS. TWO=true processes both position slots per step
// (4 independent 128-bit load streams); TWO=false one slot (light blocks).
template <int t, bool TWO>
__device__ __forceinline__ void step_all(const float4* __restrict__ pa1,
                                         const float4* __restrict__ pb1,
                                         const float4* __restrict__ pa2,
                                         const float4* __restrict__ pb2,
                                         Acc& s1, Acc& s2) {
    if constexpr (t < T_DIM) {
        constexpr float d1 = (float)Dc(1, t);
        constexpr float d2 = (float)Dc(2, t);
        constexpr float d3 = (float)Dc(3, t);
        float4 a1 = pa1[t * HW4];
        float4 b1 = pb1[t * HW4];
        if constexpr (TWO) {
            float4 a2 = pa2[t * HW4];
            float4 b2 = pb2[t * HW4];
            proc(a1, b1, d1, d2, d3, s1);
            proc(a2, b2, d1, d2, d3, s2);
        } else {
            proc(a1, b1, d1, d2, d3, s1);
        }
        step_all<t + 1, TWO>(pa1, pb1, pa2, pb2, s1, s2);
    }
}

__device__ __forceinline__ float quad_form(float a, float b, float c) {
    constexpr float M11 = (float)Mc(1, 1);
    constexpr float M22 = (float)Mc(2, 2);
    constexpr float M33 = (float)Mc(3, 3);
    constexpr float M12 = (float)(2.0 * Mc(1, 2));
    constexpr float M13 = (float)(2.0 * Mc(1, 3));
    constexpr float M23 = (float)(2.0 * Mc(2, 3));
    float q = M11 * a * a;
    q = fmaf(M22 * b, b, q);
    q = fmaf(M33 * c, c, q);
    q = fmaf(M12 * a, b, q);
    q = fmaf(M13 * a, c, q);
    q = fmaf(M23 * b, c, q);
    return q;
}

__device__ __forceinline__ float quad4(const Acc& s) {
    return (quad_form(s.c1.x, s.c2.x, s.c3.x) + quad_form(s.c1.y, s.c2.y, s.c3.y))
         + (quad_form(s.c1.z, s.c2.z, s.c3.z) + quad_form(s.c1.w, s.c2.w, s.c3.w));
}

__device__ __forceinline__ const float4* fiber_ptr(const float* x, int g) {
    // item g -> (bc = g/4096, hw = g%4096); fiber base in float4 units
    int bc = g >> 12;
    int hw = g & (HW4 - 1);
    return reinterpret_cast<const float4*>(x) + (size_t)bc * (T_DIM * HW4) + hw;
}

__device__ __forceinline__ double warp_sum(double v) {
#pragma unroll
    for (int o = 16; o > 0; o >>= 1)
        v += __shfl_down_sync(0xFFFFFFFFu, v, o);
    return v;
}

__global__ void __launch_bounds__(BLOCK, 4)
loss_fused_kernel(const float* __restrict__ xs, const float* __restrict__ xt,
                  float* __restrict__ out) {
    const int tid = threadIdx.x;
    const int g1  = blockIdx.x * BLOCK + tid;   // position slot 1 (always valid)

    const float4* pa1 = fiber_ptr(xs, g1);
    const float4* pb1 = fiber_ptr(xt, g1);

    Acc s1 = {}, s2 = {};
    double tempv, mainv;

    if (g1 < LIM2) {
        // heavy block: two independent fiber columns, 4 load streams
        const int g2 = g1 + STRIDE;
        const float4* pa2 = fiber_ptr(xs, g2);
        const float4* pb2 = fiber_ptr(xt, g2);
        step_all<0, true>(pa1, pb1, pa2, pb2, s1, s2);
        tempv = (double)quad4(s1) + (double)quad4(s2);
        mainv = (double)((s1.m0 + s1.m1) + (s2.m0 + s2.m1));
    } else {
        // light block: one fiber column
        step_all<0, false>(pa1, pb1, nullptr, nullptr, s1, s2);
        tempv = (double)quad4(s1);
        mainv = (double)(s1.m0 + s1.m1);
    }

    // ---- intra-block reduce: warp shuffle + one shared stage ----
    const int lane = tid & 31;
    const int warp = tid >> 5;
    __shared__ double sm[BLOCK / 32];
    __shared__ double st[BLOCK / 32];

    mainv = warp_sum(mainv);
    tempv = warp_sum(tempv);
    if (lane == 0) { sm[warp] = mainv; st[warp] = tempv; }
    __syncthreads();

    __shared__ bool is_last;
    if (warp == 0) {
        double vm = (lane < BLOCK / 32) ? sm[lane] : 0.0;
        double vt = (lane < BLOCK / 32) ? st[lane] : 0.0;
#pragma unroll
        for (int o = 4; o > 0; o >>= 1) {
            vm += __shfl_down_sync(0xFFFFFFFFu, vm, o);
            vt += __shfl_down_sync(0xFFFFFFFFu, vt, o);
        }
        if (lane == 0) {
            g_part_main[blockIdx.x] = vm;
            g_part_temp[blockIdx.x] = vt;
            __threadfence();
            // wraps to 0 when old == NBLK-1 -> self-resetting across replays
            is_last = (atomicInc(&g_count, NBLK - 1) == NBLK - 1);
        }
    }
    __syncthreads();

    // ---- last-arriving block: deterministic fixed-order global reduce ----
    if (is_last) {
        double vm = 0.0, vt = 0.0;
        for (int i = tid; i < NBLK; i += BLOCK) {
            vm += __ldcg(&g_part_main[i]);
            vt += __ldcg(&g_part_temp[i]);
        }
        __shared__ double fm[BLOCK];
        __shared__ double ft[BLOCK];
        fm[tid] = vm;
        ft[tid] = vt;
        __syncthreads();
#pragma unroll
        for (int sdx = BLOCK / 2; sdx > 0; sdx >>= 1) {
            if (tid < sdx) { fm[tid] += fm[tid + sdx]; ft[tid] += ft[tid + sdx]; }
            __syncthreads();
        }
        if (tid == 0) {
            double Lm = fm[0] / N_MAIN;
            double Lt = ft[0] / N_TEMP;
            out[0] = (float)(Lm + TAU * Lt);
            out[1] = (float)Lm;
            out[2] = (float)Lt;
        }
    }
}

extern "C" void kernel_launch(void* const* d_in, const int* in_sizes, int n_in,
                              void* d_out, int out_size) {
    const float* xs = (const float*)d_in[0];   // x_star_T
    const float* xt = (const float*)d_in[1];   // x_target_T
    float* out = (float*)d_out;

    loss_fused_kernel<<<NBLK, BLOCK>>>(xs, xt, out);
}

// round 10
// speedup vs baseline: 1.8284x; 1.8284x over previous
#include <cuda_runtime.h>

// ---------------------------------------------------------------------------
// Problem shape (fixed by setup_inputs): [B=4, C=16, T=32, H=128, W=128] fp32
// out = (total, L_main, L_temp) as 3 fp32 scalars.
//
// Math: with e = x_star - x_tgt (linearity), e_low = D^T(De) where D = first
// K=4 orthonormal DCT-II rows. Temporal-diff energy = c^T (Q Q^T) c with
// c = De, Q[n,s] = D[n,s+1]-D[n,s]. DC row of D is constant -> Q row 0 == 0,
// so only c1..c3 are needed. Charbonnier ~ |e| (abs error <= eps = 1e-6).
//
// R10 structure: R8's uniform two-column kernel (no divergent heavy/light
// paths — R9's branch doubled the unrolled body under the 64-reg cap and
// spilled to local, adding ~160MB of DRAM traffic). Balance is fixed by
// LAUNCH SHAPE instead: BLOCK=128, grid=1024, 8 blocks/SM (8*128*64 = 64K
// regs exactly). 1024 blocks over 148 SMs -> 136 SMs x 7, 12 x 6: critical
// path 7 block-units vs avg 6.92 (98.9% balance, vs 86.5% at R8's grid=512
// where max was 4x256-thread blocks). Single wave: 1024 <= 1184 slots.
// Every thread owns TWO fiber columns -> 4 independent 128-bit load streams.
// ---------------------------------------------------------------------------
constexpr int T_DIM  = 32;
constexpr int HW     = 128 * 128;      // 16384
constexpr int HW4    = HW / 4;         // 4096 float4 per (b,c,t) plane
constexpr int BC     = 4 * 16;         // 64
constexpr int BLOCK  = 128;
constexpr int NITEM  = BC * HW4;       // 262144 fiber columns (float4 wide)
constexpr int HALF   = NITEM / 2;      // 131072: items per position-slot
constexpr int NBLK   = HALF / BLOCK;   // 1024 blocks

constexpr double N_MAIN = 33554432.0;  // B*C*T*H*W
constexpr double N_TEMP = 32505856.0;  // B*C*(T-1)*H*W
constexpr double TAU    = 0.1;

// ---------------------------------------------------------------------------
// Compile-time DCT: D[n][t] = 0.25 * cos(pi*(2t+1)*n/64)   (sqrt(2/32)=0.25)
// ---------------------------------------------------------------------------
constexpr double PI_D = 3.141592653589793238462643383279502884;

__host__ __device__ constexpr double dcos(double x) {
    while (x >  PI_D) x -= 2.0 * PI_D;
    while (x < -PI_D) x += 2.0 * PI_D;
    double x2 = x * x;
    double term = 1.0, sum = 1.0;
    for (int k = 1; k <= 18; ++k) {
        term *= -x2 / ((2.0 * k - 1.0) * (2.0 * k));
        sum += term;
    }
    return sum;
}
__host__ __device__ constexpr double Dc(int n, int t) {
    return 0.25 * dcos(PI_D * (2.0 * t + 1.0) * (double)n / 64.0);
}
__host__ __device__ constexpr double Qc(int n, int s) { return Dc(n, s + 1) - Dc(n, s); }
__host__ __device__ constexpr double Mc(int n, int m) {
    double s = 0.0;
    for (int i = 0; i < T_DIM - 1; ++i) s += Qc(n, i) * Qc(m, i);
    return s;
}

// ---------------------------------------------------------------------------
// Scratch: per-block partials + self-resetting completion counter.
// atomicInc(&g_count, NBLK-1) wraps to 0 when the last block arrives, so the
// counter is 0 again at the start of every graph replay. No cleanup kernel.
// ---------------------------------------------------------------------------
__device__ double   g_part_main[NBLK];
__device__ double   g_part_temp[NBLK];
__device__ unsigned g_count = 0;

struct Acc {
    float4 c1, c2, c3;
    float  m0, m1;   // pairwise |e| accumulators
};

__device__ __forceinline__ void proc(const float4& a, const float4& b,
                                     float d1, float d2, float d3, Acc& s) {
    float e0 = a.x - b.x, e1 = a.y - b.y, e2 = a.z - b.z, e3 = a.w - b.w;
    s.m0 += fabsf(e0) + fabsf(e1);
    s.m1 += fabsf(e2) + fabsf(e3);
    s.c1.x = fmaf(d1, e0, s.c1.x); s.c1.y = fmaf(d1, e1, s.c1.y);
    s.c1.z = fmaf(d1, e2, s.c1.z); s.c1.w = fmaf(d1, e3, s.c1.w);
    s.c2.x = fmaf(d2, e0, s.c2.x); s.c2.y = fmaf(d2, e1, s.c2.y);
    s.c2.z = fmaf(d2, e2, s.c2.z); s.c2.w = fmaf(d2, e3, s.c2.w);
    s.c3.x = fmaf(d3, e0, s.c3.x); s.c3.y = fmaf(d3, e1, s.c3.y);
    s.c3.z = fmaf(d3, e2, s.c3.z); s.c3.w = fmaf(d3, e3, s.c3.w);
}

// Template-unrolled T loop: coefficients are constexpr locals per step ->
// FFMA immediates in SASS. Two position slots per step, all four loads
// issued before the arithmetic for maximum per-step MLP.
template <int t>
__device__ __forceinline__ void step_all(const float4* __restrict__ pa1,
                                         const float4* __restrict__ pb1,
                                         const float4* __restrict__ pa2,
                                         const float4* __restrict__ pb2,
                                         Acc& s1, Acc& s2) {
    if constexpr (t < T_DIM) {
        constexpr float d1 = (float)Dc(1, t);
        constexpr float d2 = (float)Dc(2, t);
        constexpr float d3 = (float)Dc(3, t);
        float4 a1 = pa1[t * HW4];
        float4 b1 = pb1[t * HW4];
        float4 a2 = pa2[t * HW4];
        float4 b2 = pb2[t * HW4];
        proc(a1, b1, d1, d2, d3, s1);
        proc(a2, b2, d1, d2, d3, s2);
        step_all<t + 1>(pa1, pb1, pa2, pb2, s1, s2);
    }
}

__device__ __forceinline__ float quad_form(float a, float b, float c) {
    constexpr float M11 = (float)Mc(1, 1);
    constexpr float M22 = (float)Mc(2, 2);
    constexpr float M33 = (float)Mc(3, 3);
    constexpr float M12 = (float)(2.0 * Mc(1, 2));
    constexpr float M13 = (float)(2.0 * Mc(1, 3));
    constexpr float M23 = (float)(2.0 * Mc(2, 3));
    float q = M11 * a * a;
    q = fmaf(M22 * b, b, q);
    q = fmaf(M33 * c, c, q);
    q = fmaf(M12 * a, b, q);
    q = fmaf(M13 * a, c, q);
    q = fmaf(M23 * b, c, q);
    return q;
}

__device__ __forceinline__ float quad4(const Acc& s) {
    return (quad_form(s.c1.x, s.c2.x, s.c3.x) + quad_form(s.c1.y, s.c2.y, s.c3.y))
         + (quad_form(s.c1.z, s.c2.z, s.c3.z) + quad_form(s.c1.w, s.c2.w, s.c3.w));
}

__device__ __forceinline__ const float4* fiber_ptr(const float* x, int g) {
    // item g -> (bc = g/4096, hw = g%4096); fiber base in float4 units
    int bc = g >> 12;
    int hw = g & (HW4 - 1);
    return reinterpret_cast<const float4*>(x) + (size_t)bc * (T_DIM * HW4) + hw;
}

__device__ __forceinline__ double warp_sum(double v) {
#pragma unroll
    for (int o = 16; o > 0; o >>= 1)
        v += __shfl_down_sync(0xFFFFFFFFu, v, o);
    return v;
}

__global__ void __launch_bounds__(BLOCK, 8)
loss_fused_kernel(const float* __restrict__ xs, const float* __restrict__ xt,
                  float* __restrict__ out) {
    const int tid = threadIdx.x;
    const int g1  = blockIdx.x * BLOCK + tid;   // position slot 1
    const int g2  = g1 + HALF;                  // position slot 2 (independent)

    const float4* pa1 = fiber_ptr(xs, g1);
    const float4* pb1 = fiber_ptr(xt, g1);
    const float4* pa2 = fiber_ptr(xs, g2);
    const float4* pb2 = fiber_ptr(xt, g2);

    Acc s1 = {}, s2 = {};

    step_all<0>(pa1, pb1, pa2, pb2, s1, s2);

    double tempv = (double)quad4(s1) + (double)quad4(s2);
    double mainv = (double)((s1.m0 + s1.m1) + (s2.m0 + s2.m1));

    // ---- intra-block reduce: warp shuffle + one shared stage ----
    const int lane = tid & 31;
    const int warp = tid >> 5;
    __shared__ double sm[BLOCK / 32];
    __shared__ double st[BLOCK / 32];

    mainv = warp_sum(mainv);
    tempv = warp_sum(tempv);
    if (lane == 0) { sm[warp] = mainv; st[warp] = tempv; }
    __syncthreads();

    __shared__ bool is_last;
    if (warp == 0) {
        double vm = (lane < BLOCK / 32) ? sm[lane] : 0.0;
        double vt = (lane < BLOCK / 32) ? st[lane] : 0.0;
#pragma unroll
        for (int o = 2; o > 0; o >>= 1) {
            vm += __shfl_down_sync(0xFFFFFFFFu, vm, o);
            vt += __shfl_down_sync(0xFFFFFFFFu, vt, o);
        }
        if (lane == 0) {
            g_part_main[blockIdx.x] = vm;
            g_part_temp[blockIdx.x] = vt;
            __threadfence();
            // wraps to 0 when old == NBLK-1 -> self-resetting across replays
            is_last = (atomicInc(&g_count, NBLK - 1) == NBLK - 1);
        }
    }
    __syncthreads();

    // ---- last-arriving block: deterministic fixed-order global reduce ----
    if (is_last) {
        double vm = 0.0, vt = 0.0;
#pragma unroll
        for (int i = tid; i < NBLK; i += BLOCK) {
            vm += __ldcg(&g_part_main[i]);
            vt += __ldcg(&g_part_temp[i]);
        }
        __shared__ double fm[BLOCK];
        __shared__ double ft[BLOCK];
        fm[tid] = vm;
        ft[tid] = vt;
        __syncthreads();
#pragma unroll
        for (int sdx = BLOCK / 2; sdx > 0; sdx >>= 1) {
            if (tid < sdx) { fm[tid] += fm[tid + sdx]; ft[tid] += ft[tid + sdx]; }
            __syncthreads();
        }
        if (tid == 0) {
            double Lm = fm[0] / N_MAIN;
            double Lt = ft[0] / N_TEMP;
            out[0] = (float)(Lm + TAU * Lt);
            out[1] = (float)Lm;
            out[2] = (float)Lt;
        }
    }
}

extern "C" void kernel_launch(void* const* d_in, const int* in_sizes, int n_in,
                              void* d_out, int out_size) {
    const float* xs = (const float*)d_in[0];   // x_star_T
    const float* xt = (const float*)d_in[1];   // x_target_T
    float* out = (float*)d_out;

    loss_fused_kernel<<<NBLK, BLOCK>>>(xs, xt, out);
}